// round 2
// baseline (speedup 1.0000x reference)
#include <cuda_runtime.h>
#include <math.h>

#define BATCH 64
#define NPTS 1024
#define NT 256
#define PPT 4              // points per thread (NT*PPT == NPTS)
#define NWARPS (NT/32)

// Scratch for sorted death values: [2*BATCH][NPTS] (cloud 0..63 = gts, 64..127 = preds)
__device__ float g_deaths[2 * BATCH][NPTS];

static __device__ __forceinline__ unsigned long long u64min(unsigned long long a,
                                                            unsigned long long b) {
    return a < b ? a : b;
}

__global__ __launch_bounds__(NT, 1)
void prim_kernel(const float* __restrict__ gts, const float* __restrict__ preds) {
    const int cloud = blockIdx.x;  // 0..127
    const float* base = (cloud < BATCH ? gts : preds) + (size_t)(cloud & (BATCH - 1)) * NPTS * 3;

    __shared__ float sp[NPTS * 3];                 // point coords, flat [i*3 + c]
    __shared__ unsigned long long swarp[NWARPS];   // per-warp argmin keys
    __shared__ float sdeath[NPTS];                 // deaths, then sort buffer

    const int t = threadIdx.x;
    const int lane = t & 31;
    const int wid = t >> 5;

    // Load the cloud into shared memory (coalesced).
    for (int i = t; i < NPTS * 3; i += NT) sp[i] = base[i];
    __syncthreads();

    // Each thread owns points [t*PPT, t*PPT+PPT). Coords + min_d2 in registers.
    float px[PPT], py[PPT], pz[PPT], d2[PPT];
    bool intree[PPT];
    const float x0 = sp[0], y0 = sp[1], z0 = sp[2];
#pragma unroll
    for (int k = 0; k < PPT; k++) {
        const int i = t * PPT + k;
        px[k] = sp[i * 3 + 0];
        py[k] = sp[i * 3 + 1];
        pz[k] = sp[i * 3 + 2];
        const float dx = px[k] - x0, dy = py[k] - y0, dz = pz[k] - z0;
        d2[k] = dx * dx + dy * dy + dz * dz;
        intree[k] = (i == 0);
    }

    // Prim: N-1 extractions.
    for (int it = 0; it < NPTS - 1; it++) {
        // Local argmin over owned points, packed key = (d2_bits << 32) | idx.
        // Positive-float bit patterns are order-isomorphic to the floats, and the
        // idx in the low bits reproduces jnp.argmin first-min tie-breaking.
        unsigned long long key = ~0ull;
#pragma unroll
        for (int k = 0; k < PPT; k++) {
            unsigned long long kk = intree[k]
                ? ~0ull
                : ((unsigned long long)__float_as_uint(d2[k]) << 32) |
                      (unsigned)(t * PPT + k);
            key = u64min(key, kk);
        }
        // Warp min-reduce.
#pragma unroll
        for (int off = 16; off; off >>= 1)
            key = u64min(key, __shfl_down_sync(0xffffffffu, key, off));
        if (lane == 0) swarp[wid] = key;
        __syncthreads();
        // All threads redundantly reduce the 8 warp results (broadcast loads).
        unsigned long long best = swarp[0];
#pragma unroll
        for (int w = 1; w < NWARPS; w++) best = u64min(best, swarp[w]);

        const int j = (int)(unsigned)best;
        if (t == 0) {
            const float d2min = __uint_as_float((unsigned)(best >> 32));
            sdeath[it] = sqrtf(d2min + 1e-12f);
        }

        // Update min_d2 against the newly added point j.
        const float xj = sp[j * 3 + 0], yj = sp[j * 3 + 1], zj = sp[j * 3 + 2];
        const int rel = j - t * PPT;
#pragma unroll
        for (int k = 0; k < PPT; k++) {
            const float dx = px[k] - xj, dy = py[k] - yj, dz = pz[k] - zj;
            const float nd = dx * dx + dy * dy + dz * dz;
            d2[k] = fminf(d2[k], nd);
            if (rel == k) intree[k] = true;  // mark j; keeps it out of future argmins
        }
        __syncthreads();  // protect swarp before next iteration's writes
    }

    // Pad slot N-1 with +inf, then bitonic sort ascending.
    if (t == 0) sdeath[NPTS - 1] = __int_as_float(0x7f800000);
    for (int k = 2; k <= NPTS; k <<= 1) {
        for (int j = k >> 1; j > 0; j >>= 1) {
            __syncthreads();
            for (int i = t; i < NPTS; i += NT) {
                const int ixj = i ^ j;
                if (ixj > i) {
                    const float a = sdeath[i];
                    const float b = sdeath[ixj];
                    const bool up = ((i & k) == 0);
                    if ((a > b) == up) {
                        sdeath[i] = b;
                        sdeath[ixj] = a;
                    }
                }
            }
        }
    }
    __syncthreads();
    for (int i = t; i < NPTS; i += NT) g_deaths[cloud][i] = sdeath[i];
}

__global__ void wloss_kernel(float* __restrict__ out) {
    const int t = threadIdx.x;
    float s = 0.0f;
    // Sum |deaths_gts[b][k] - deaths_preds[b][k]| over b in [0,64), k in [0,1023).
    const int TOT = BATCH * (NPTS - 1);
    for (int idx = t; idx < TOT; idx += 1024) {
        const int b = idx / (NPTS - 1);
        const int k = idx - b * (NPTS - 1);
        s += fabsf(g_deaths[b][k] - g_deaths[BATCH + b][k]);
    }
    __shared__ float red[32];
#pragma unroll
    for (int off = 16; off; off >>= 1) s += __shfl_down_sync(0xffffffffu, s, off);
    if ((t & 31) == 0) red[t >> 5] = s;
    __syncthreads();
    if (t < 32) {
        float v = red[t];
#pragma unroll
        for (int off = 16; off; off >>= 1) v += __shfl_down_sync(0xffffffffu, v, off);
        if (t == 0) *out = v * (1.0f / BATCH);  // TOPO_LAMBDA = 1.0
    }
}

extern "C" void kernel_launch(void* const* d_in, const int* in_sizes, int n_in,
                              void* d_out, int out_size) {
    const float* gts = (const float*)d_in[0];
    const float* preds = (const float*)d_in[1];
    float* out = (float*)d_out;
    prim_kernel<<<2 * BATCH, NT>>>(gts, preds);
    wloss_kernel<<<1, 1024>>>(out);
}

// round 3
// speedup vs baseline: 1.3227x; 1.3227x over previous
#include <cuda_runtime.h>
#include <math.h>

#define BATCH 64
#define NPTS 1024
#define NT 256
#define PPT 4              // points per thread (NT*PPT == NPTS)
#define NWARPS (NT/32)

// Scratch: sorted death values [2*BATCH][NPTS] (0..63 = gts, 64..127 = preds)
__device__ float g_deaths[2 * BATCH][NPTS];
__device__ float g_partial[BATCH];

static __device__ __forceinline__ unsigned long long u64min(unsigned long long a,
                                                            unsigned long long b) {
    return a < b ? a : b;
}

__global__ __launch_bounds__(NT, 1)
void prim_kernel(const float* __restrict__ gts, const float* __restrict__ preds) {
    const int cloud = blockIdx.x;  // 0..127
    const float* base = (cloud < BATCH ? gts : preds) + (size_t)(cloud & (BATCH - 1)) * NPTS * 3;

    __shared__ float raw[NPTS * 3];
    __shared__ float4 sp4[NPTS];                       // {x, y, z, |p|^2}
    __shared__ float sdeath[NPTS];
    __shared__ unsigned long long swarp[2][NWARPS];    // double-buffered per-warp argmin

    const int t = threadIdx.x;
    const int lane = t & 31;
    const int wid = t >> 5;

    // Coalesced load, then build float4-with-norm table.
    for (int i = t; i < NPTS * 3; i += NT) raw[i] = base[i];
    __syncthreads();
#pragma unroll
    for (int k = 0; k < PPT; k++) {
        const int i = t * PPT + k;
        const float x = raw[i * 3 + 0], y = raw[i * 3 + 1], z = raw[i * 3 + 2];
        sp4[i] = make_float4(x, y, z, fmaf(x, x, fmaf(y, y, z * z)));
    }
    __syncthreads();

    // Owned points in registers: (-2x, -2y, -2z, |p|^2) so the update is 3 FMAs + 1 add.
    float mx[PPT], my[PPT], mz[PPT], sq[PPT], d2[PPT];
    const float4 p0 = sp4[0];
#pragma unroll
    for (int k = 0; k < PPT; k++) {
        const int i = t * PPT + k;
        const float4 p = sp4[i];
        mx[k] = -2.0f * p.x; my[k] = -2.0f * p.y; mz[k] = -2.0f * p.z; sq[k] = p.w;
        // Gram form, matching the reference: d2 = |p|^2 + |p0|^2 - 2 p.p0, clamped >= 0
        const float dd = fmaf(mx[k], p0.x, fmaf(my[k], p0.y, fmaf(mz[k], p0.z, sq[k] + p0.w)));
        d2[k] = fmaxf(dd, 0.0f);
    }
    if (t == 0) { d2[0] = 1e30f; sq[0] = 1e30f; }  // point 0 joined; sentinel self-propagates

    for (int it = 0; it < NPTS - 1; it++) {
        // Positive-float bits are order-isomorphic to floats -> unsigned min is exact.
        unsigned c[PPT];
#pragma unroll
        for (int k = 0; k < PPT; k++) c[k] = __float_as_uint(d2[k]);
        const unsigned vmin = min(min(c[0], c[1]), min(c[2], c[3]));
        const unsigned wmin = __reduce_min_sync(0xffffffffu, vmin);
        unsigned myidx = 0xffffffffu;
        if (vmin == wmin) {
            const int k = (c[0] == vmin) ? 0 : (c[1] == vmin) ? 1 : (c[2] == vmin) ? 2 : 3;
            myidx = (unsigned)(t * PPT + k);   // lowest-index tie-break == jnp.argmin
        }
        const unsigned widx = __reduce_min_sync(0xffffffffu, myidx);
        if (lane == 0) swarp[it & 1][wid] = ((unsigned long long)wmin << 32) | widx;
        __syncthreads();

        // All threads redundantly combine the 8 warp results (vectorized broadcast loads).
        const ulonglong2* sv = (const ulonglong2*)swarp[it & 1];
        const ulonglong2 a = sv[0], b = sv[1], e = sv[2], f = sv[3];
        const unsigned long long best =
            u64min(u64min(u64min(a.x, a.y), u64min(b.x, b.y)),
                   u64min(u64min(e.x, e.y), u64min(f.x, f.y)));
        const int j = (int)(unsigned)best;
        if (t == 0)
            sdeath[it] = sqrtf(__uint_as_float((unsigned)(best >> 32)) + 1e-12f);

        const float4 pj = sp4[j];               // one LDS.128 broadcast
        const int rel = j - t * PPT;
#pragma unroll
        for (int k = 0; k < PPT; k++) {
            const float nd = fmaf(mx[k], pj.x, fmaf(my[k], pj.y, fmaf(mz[k], pj.z, sq[k] + pj.w)));
            d2[k] = fminf(d2[k], fmaxf(nd, 0.0f));
            if (rel == k) { d2[k] = 1e30f; sq[k] = 1e30f; }
        }
        // no second barrier: swarp is double-buffered
    }

    __syncthreads();
    // Pad slot N-1 with +inf, then bitonic sort ascending.
    if (t == 0) sdeath[NPTS - 1] = __int_as_float(0x7f800000);
    for (int k = 2; k <= NPTS; k <<= 1) {
        for (int j = k >> 1; j > 0; j >>= 1) {
            __syncthreads();
            for (int i = t; i < NPTS; i += NT) {
                const int ixj = i ^ j;
                if (ixj > i) {
                    const float a = sdeath[i];
                    const float b = sdeath[ixj];
                    const bool up = ((i & k) == 0);
                    if ((a > b) == up) { sdeath[i] = b; sdeath[ixj] = a; }
                }
            }
        }
    }
    __syncthreads();
    for (int i = t; i < NPTS; i += NT) g_deaths[cloud][i] = sdeath[i];
}

// Per-batch partial sums (deterministic, no atomics).
__global__ void wloss_partial() {
    const int b = blockIdx.x;
    const int t = threadIdx.x;
    float s = 0.0f;
    for (int k = t; k < NPTS - 1; k += 256)
        s += fabsf(g_deaths[b][k] - g_deaths[BATCH + b][k]);
    __shared__ float red[8];
#pragma unroll
    for (int off = 16; off; off >>= 1) s += __shfl_down_sync(0xffffffffu, s, off);
    if ((t & 31) == 0) red[t >> 5] = s;
    __syncthreads();
    if (t < 32) {
        float v = (t < 8) ? red[t] : 0.0f;
#pragma unroll
        for (int off = 4; off; off >>= 1) v += __shfl_down_sync(0xffffffffu, v, off);
        if (t == 0) g_partial[b] = v;
    }
}

__global__ void wloss_final(float* __restrict__ out) {
    const int t = threadIdx.x;  // 32 threads
    float v = g_partial[t] + g_partial[t + 32];
#pragma unroll
    for (int off = 16; off; off >>= 1) v += __shfl_down_sync(0xffffffffu, v, off);
    if (t == 0) *out = v * (1.0f / BATCH);  // TOPO_LAMBDA = 1.0
}

extern "C" void kernel_launch(void* const* d_in, const int* in_sizes, int n_in,
                              void* d_out, int out_size) {
    const float* gts = (const float*)d_in[0];
    const float* preds = (const float*)d_in[1];
    float* out = (float*)d_out;
    prim_kernel<<<2 * BATCH, NT>>>(gts, preds);
    wloss_partial<<<BATCH, 256>>>();
    wloss_final<<<1, 32>>>(out);
}

// round 4
// speedup vs baseline: 2.1518x; 1.6269x over previous
#include <cuda_runtime.h>
#include <math.h>

#define BATCH 64
#define NPTS 1024
#define NT 256
#define PPT 4              // points per thread (NT*PPT == NPTS)
#define NWARPS (NT/32)

// Scratch: sorted death values [2*BATCH][NPTS] (0..63 = gts, 64..127 = preds)
__device__ float g_deaths[2 * BATCH][NPTS];
__device__ float g_partial[BATCH];

__global__ __launch_bounds__(NT, 1)
void prim_kernel(const float* __restrict__ gts, const float* __restrict__ preds) {
    const int cloud = blockIdx.x;  // 0..127
    const float* base = (cloud < BATCH ? gts : preds) + (size_t)(cloud & (BATCH - 1)) * NPTS * 3;

    __shared__ float raw[NPTS * 3];
    __shared__ float4 sp4[NPTS];                     // {x, y, z, |p|^2}
    __shared__ float sdeath[NPTS];                   // packed winner bits, then deaths
    __shared__ __align__(16) unsigned swarp[2][NWARPS];  // double-buffered per-warp argmin keys

    const int t = threadIdx.x;
    const int lane = t & 31;
    const int wid = t >> 5;

    // Coalesced load, then build float4-with-norm table.
    for (int i = t; i < NPTS * 3; i += NT) raw[i] = base[i];
    __syncthreads();
#pragma unroll
    for (int k = 0; k < PPT; k++) {
        const int i = t * PPT + k;
        const float x = raw[i * 3 + 0], y = raw[i * 3 + 1], z = raw[i * 3 + 2];
        sp4[i] = make_float4(x, y, z, fmaf(x, x, fmaf(y, y, z * z)));
    }
    __syncthreads();

    // Owned points in registers: (-2x, -2y, -2z, |p|^2) so the update is 3 FMAs + 1 add.
    float mx[PPT], my[PPT], mz[PPT], sq[PPT], d2[PPT];
    const float4 p0 = sp4[0];
#pragma unroll
    for (int k = 0; k < PPT; k++) {
        const int i = t * PPT + k;
        const float4 p = sp4[i];
        mx[k] = -2.0f * p.x; my[k] = -2.0f * p.y; mz[k] = -2.0f * p.z; sq[k] = p.w;
        // Gram form, matching the reference: d2 = |p|^2 + |p0|^2 - 2 p.p0, clamped >= 0
        const float dd = fmaf(mx[k], p0.x, fmaf(my[k], p0.y, fmaf(mz[k], p0.z, sq[k] + p0.w)));
        d2[k] = fmaxf(dd, 0.0f);
    }
    if (t == 0) { d2[0] = 1e30f; sq[0] = 1e30f; }  // point 0 joined; sentinel self-propagates

    unsigned* const sbits = (unsigned*)sdeath;
    const unsigned idx0 = (unsigned)(t * PPT);

#pragma unroll 2
    for (int it = 0; it < NPTS - 1; it++) {
        // Packed key: top 22 bits of the (non-negative) d2 float, low 10 bits = point idx.
        // Positive-float bit order == float order, so unsigned min == (quantized) argmin
        // with lowest-index tie-breaking, in a SINGLE reduction.
        unsigned key;
        {
            const unsigned k0 = (__float_as_uint(d2[0]) & 0xFFFFFC00u) | (idx0 + 0);
            const unsigned k1 = (__float_as_uint(d2[1]) & 0xFFFFFC00u) | (idx0 + 1);
            const unsigned k2 = (__float_as_uint(d2[2]) & 0xFFFFFC00u) | (idx0 + 2);
            const unsigned k3 = (__float_as_uint(d2[3]) & 0xFFFFFC00u) | (idx0 + 3);
            key = min(min(k0, k1), min(k2, k3));
        }
        key = __reduce_min_sync(0xffffffffu, key);
        if (lane == 0) swarp[it & 1][wid] = key;
        __syncthreads();

        // All threads redundantly combine the 8 warp keys (2x LDS.128 + 7 mins).
        const uint4 a = *(const uint4*)&swarp[it & 1][0];
        const uint4 b = *(const uint4*)&swarp[it & 1][4];
        const unsigned best = min(min(min(a.x, a.y), min(a.z, a.w)),
                                  min(min(b.x, b.y), min(b.z, b.w)));
        const int j = (int)(best & 1023u);
        if (t == 0) sbits[it] = best;   // sqrt deferred out of the loop

        const float4 pj = sp4[j];       // one LDS.128 broadcast
        const int rel = j - (int)idx0;
#pragma unroll
        for (int k = 0; k < PPT; k++) {
            const float nd = fmaf(mx[k], pj.x, fmaf(my[k], pj.y, fmaf(mz[k], pj.z, sq[k] + pj.w)));
            d2[k] = fminf(d2[k], fmaxf(nd, 0.0f));
            if (rel == k) { d2[k] = 1e30f; sq[k] = 1e30f; }
        }
        // no second barrier: swarp is double-buffered
    }

    __syncthreads();
    // Convert packed winner bits -> death values (strip the 10 index bits).
    for (int i = t; i < NPTS - 1; i += NT) {
        const unsigned bits = sbits[i] & 0xFFFFFC00u;
        sdeath[i] = sqrtf(__uint_as_float(bits) + 1e-12f);
    }
    if (t == 0) sdeath[NPTS - 1] = __int_as_float(0x7f800000);
    // Bitonic sort ascending.
    for (int k = 2; k <= NPTS; k <<= 1) {
        for (int j = k >> 1; j > 0; j >>= 1) {
            __syncthreads();
            for (int i = t; i < NPTS; i += NT) {
                const int ixj = i ^ j;
                if (ixj > i) {
                    const float va = sdeath[i];
                    const float vb = sdeath[ixj];
                    const bool up = ((i & k) == 0);
                    if ((va > vb) == up) { sdeath[i] = vb; sdeath[ixj] = va; }
                }
            }
        }
    }
    __syncthreads();
    for (int i = t; i < NPTS; i += NT) g_deaths[cloud][i] = sdeath[i];
}

// Per-batch partial sums (deterministic, no atomics).
__global__ void wloss_partial() {
    const int b = blockIdx.x;
    const int t = threadIdx.x;
    float s = 0.0f;
    for (int k = t; k < NPTS - 1; k += 256)
        s += fabsf(g_deaths[b][k] - g_deaths[BATCH + b][k]);
    __shared__ float red[8];
#pragma unroll
    for (int off = 16; off; off >>= 1) s += __shfl_down_sync(0xffffffffu, s, off);
    if ((t & 31) == 0) red[t >> 5] = s;
    __syncthreads();
    if (t < 32) {
        float v = (t < 8) ? red[t] : 0.0f;
#pragma unroll
        for (int off = 4; off; off >>= 1) v += __shfl_down_sync(0xffffffffu, v, off);
        if (t == 0) g_partial[b] = v;
    }
}

__global__ void wloss_final(float* __restrict__ out) {
    const int t = threadIdx.x;  // 32 threads
    float v = g_partial[t] + g_partial[t + 32];
#pragma unroll
    for (int off = 16; off; off >>= 1) v += __shfl_down_sync(0xffffffffu, v, off);
    if (t == 0) *out = v * (1.0f / BATCH);  // TOPO_LAMBDA = 1.0
}

extern "C" void kernel_launch(void* const* d_in, const int* in_sizes, int n_in,
                              void* d_out, int out_size) {
    const float* gts = (const float*)d_in[0];
    const float* preds = (const float*)d_in[1];
    float* out = (float*)d_out;
    prim_kernel<<<2 * BATCH, NT>>>(gts, preds);
    wloss_partial<<<BATCH, 256>>>();
    wloss_final<<<1, 32>>>(out);
}